// round 10
// baseline (speedup 1.0000x reference)
#include <cuda_runtime.h>
#include <math_constants.h>
#include <cstdint>
#include <cstddef>

#define T_DIM 16
#define HW_DIM 1024
#define C_DIM 512
#define NH 8
#define HD 64
#define M_ROWS (T_DIM * HW_DIM)   /* 16384 */
#define QKV_N (3 * C_DIM)         /* 1536  */

// Scratch (device globals; no allocation allowed)
__device__ float g_qkv[M_ROWS * QKV_N];     // ~100.7 MB
__device__ float g_attn[M_ROWS * C_DIM];    // ~33.6 MB
__device__ int   g_bad[4];                  // probe verdicts

// ---------------------------------------------------------------------------
// Helpers (arch-agnostic PTX only: tf32 cvt + mma.sync, sm_80+)
// ---------------------------------------------------------------------------
__device__ __forceinline__ uint32_t to_tf32u(float x) {
    float r; asm("cvt.rna.tf32.f32 %0, %1;" : "=f"(r) : "f"(x));
    return __float_as_uint(r);
}

// D += A(16x8,row) * B(8x8,col); tf32 inputs as b32 regs, f32 accum.
#define MMA_TF32(d, a, b)                                                      \
    asm volatile("mma.sync.aligned.m16n8k8.row.col.f32.tf32.tf32.f32 "         \
        "{%0,%1,%2,%3}, {%4,%5,%6,%7}, {%8,%9}, {%0,%1,%2,%3};"                \
        : "+f"((d)[0]), "+f"((d)[1]), "+f"((d)[2]), "+f"((d)[3])               \
        : "r"((a)[0]), "r"((a)[1]), "r"((a)[2]), "r"((a)[3]),                  \
          "r"((b)[0]), "r"((b)[1]))

// ---------------------------------------------------------------------------
// mma.sync tf32 GEMM (unchanged from R9 WIN): out = A@B + bias
// ---------------------------------------------------------------------------
#define GEMM_SMEM_BYTES ((2 * 128 * 36 + 2 * 32 * 136) * 4)   /* 71680 */

__global__ __launch_bounds__(256) void mma_gemm_kernel(
    const float* __restrict__ A, const float* __restrict__ B,
    const float* __restrict__ bias, float* __restrict__ out,
    int M, int N, int K)
{
    extern __shared__ uint32_t smu[];
    uint32_t* As[2] = { smu, smu + 128 * 36 };
    uint32_t* Bs[2] = { smu + 2 * 128 * 36, smu + 2 * 128 * 36 + 32 * 136 };

    const int tid  = threadIdx.x;
    const int wid  = tid >> 5;
    const int lane = tid & 31;
    const int g    = lane >> 2;
    const int r    = lane & 3;
    const int wm   = (wid & 3) * 32;
    const int wn   = (wid >> 2) * 64;
    const int m0   = blockIdx.y * 128;
    const int n0   = blockIdx.x * 128;

    const int aRow = tid >> 3;
    const int aKc  = (tid & 7) << 2;
    const int bKr  = tid >> 5;
    const int bNc  = (tid & 31) << 2;

    float4 pa[4], pb[4];
#pragma unroll
    for (int i = 0; i < 4; i++) {
        pa[i] = *(const float4*)&A[(size_t)(m0 + aRow + 32 * i) * K + aKc];
        pb[i] = *(const float4*)&B[(size_t)(bKr + 8 * i) * N + n0 + bNc];
    }

    float acc[2][8][4];
#pragma unroll
    for (int mt = 0; mt < 2; mt++)
#pragma unroll
        for (int j = 0; j < 8; j++)
#pragma unroll
            for (int c = 0; c < 4; c++) acc[mt][j][c] = 0.f;

    const int NS = K / 32;
    for (int s = 0; s < NS; s++) {
        const int b = s & 1;
#pragma unroll
        for (int i = 0; i < 4; i++) {
            uint32_t* ar = &As[b][(aRow + 32 * i) * 36 + aKc];
            ar[0] = to_tf32u(pa[i].x); ar[1] = to_tf32u(pa[i].y);
            ar[2] = to_tf32u(pa[i].z); ar[3] = to_tf32u(pa[i].w);
            uint32_t* br = &Bs[b][(bKr + 8 * i) * 136 + bNc];
            br[0] = to_tf32u(pb[i].x); br[1] = to_tf32u(pb[i].y);
            br[2] = to_tf32u(pb[i].z); br[3] = to_tf32u(pb[i].w);
        }
        __syncthreads();

        if (s + 1 < NS) {
            const int kn = (s + 1) * 32;
#pragma unroll
            for (int i = 0; i < 4; i++) {
                pa[i] = *(const float4*)&A[(size_t)(m0 + aRow + 32 * i) * K + kn + aKc];
                pb[i] = *(const float4*)&B[(size_t)(kn + bKr + 8 * i) * N + n0 + bNc];
            }
        }

#pragma unroll
        for (int ks = 0; ks < 4; ks++) {
            const int k8 = ks * 8;
            uint32_t af[2][4];
#pragma unroll
            for (int mt = 0; mt < 2; mt++) {
                const uint32_t* base = &As[b][(wm + mt * 16) * 36 + k8];
                af[mt][0] = base[(g    ) * 36 + r    ];
                af[mt][1] = base[(g + 8) * 36 + r    ];
                af[mt][2] = base[(g    ) * 36 + r + 4];
                af[mt][3] = base[(g + 8) * 36 + r + 4];
            }
#pragma unroll
            for (int j = 0; j < 8; j++) {
                uint32_t bf[2];
                const uint32_t* base = &Bs[b][k8 * 136 + wn + 8 * j + g];
                bf[0] = base[r * 136];
                bf[1] = base[(r + 4) * 136];
                MMA_TF32(acc[0][j], af[0], bf);
                MMA_TF32(acc[1][j], af[1], bf);
            }
        }
        __syncthreads();
    }

#pragma unroll
    for (int mt = 0; mt < 2; mt++) {
        const int row = m0 + wm + mt * 16 + g;
#pragma unroll
        for (int j = 0; j < 8; j++) {
            const int col = n0 + wn + 8 * j + 2 * r;
            const float b0 = bias[col], b1 = bias[col + 1];
            float2 v0; v0.x = acc[mt][j][0] + b0; v0.y = acc[mt][j][1] + b1;
            float2 v1; v1.x = acc[mt][j][2] + b0; v1.y = acc[mt][j][3] + b1;
            *(float2*)&out[(size_t)row * N + col]       = v0;
            *(float2*)&out[(size_t)(row + 8) * N + col] = v1;
        }
    }
}

// ---------------------------------------------------------------------------
// mma.sync tf32 attention v2: block = (pair, 128-q tile), 128 threads = 4 warps.
// Warp w owns 32 q rows (2 m16 tiles) -> B fragments (K, V) reused across 2
// MMAs: LDS/MMA drops 2.5 -> 1.5. Max-free softmax (scores O(1); probe+fixup
// backstops). Output in (h, q, t, d) layout (reshape bug preserved).
// ---------------------------------------------------------------------------
#define QS_OFF  0
#define KS_OFF  (128 * 68)
#define VS_OFF  (KS_OFF + 64 * 68)
#define PS_OFF  (VS_OFF + 64 * 72)
#define ATTN_SMEM_BYTES ((PS_OFF + 128 * 68) * 4)   /* 105472 */

__global__ __launch_bounds__(128) void mma_attn_kernel()
{
    extern __shared__ uint32_t smu[];
    uint32_t* Qs = smu + QS_OFF;   // [q][68]  tf32 (Q * 0.125)
    uint32_t* Ks = smu + KS_OFF;   // [k][68]  tf32
    uint32_t* Vs = smu + VS_OFF;   // [k][72]  tf32
    uint32_t* Ps = smu + PS_OFF;   // [q][68]  tf32 exp(S)

    const int tid  = threadIdx.x;
    const int wid  = tid >> 5;          // 0..3
    const int lane = tid & 31;
    const int g    = lane >> 2;
    const int r    = lane & 3;
    const int pair = blockIdx.y;
    const int h    = pair >> 4;
    const int t    = pair & 15;
    const int q0   = blockIdx.x * 128;
    const int qb   = wid * 32;          // warp's q-row base (2 m16 tiles)

    // Stage Q once: 128 x 64, scaled by 1/8 (2048 float4 / 128 thr = 16 iters)
#pragma unroll
    for (int i = 0; i < 16; i++) {
        int idx = tid + 128 * i;
        int row = idx >> 4;
        int dc  = (idx & 15) << 2;
        float4 v = *(const float4*)&g_qkv[(size_t)(t * HW_DIM + q0 + row) * QKV_N
                                          + h * HD + dc];
        uint32_t* qr = &Qs[row * 68 + dc];
        qr[0] = to_tf32u(v.x * 0.125f); qr[1] = to_tf32u(v.y * 0.125f);
        qr[2] = to_tf32u(v.z * 0.125f); qr[3] = to_tf32u(v.w * 0.125f);
    }

    float oacc[2][8][4];
#pragma unroll
    for (int mt = 0; mt < 2; mt++)
#pragma unroll
        for (int j = 0; j < 8; j++)
#pragma unroll
            for (int c = 0; c < 4; c++) oacc[mt][j][c] = 0.f;
    float lsum[2][2] = { {0.f, 0.f}, {0.f, 0.f} };   // [mt][rowset g / g+8]

    for (int kc = 0; kc < 16; kc++) {
        const int k0 = kc * 64;
        __syncthreads();   // prior chunk's Ks/Vs reads complete

        // Stage K (64x64 -> Ks[k][68]) and V (64x64 -> Vs[k][72])
#pragma unroll
        for (int i = 0; i < 8; i++) {
            int idx = tid + 128 * i;
            int row = idx >> 4;
            int dc  = (idx & 15) << 2;
            size_t base = (size_t)(t * HW_DIM + k0 + row) * QKV_N + h * HD + dc;
            float4 kv = *(const float4*)&g_qkv[base + C_DIM];
            uint32_t* kr = &Ks[row * 68 + dc];
            kr[0] = to_tf32u(kv.x); kr[1] = to_tf32u(kv.y);
            kr[2] = to_tf32u(kv.z); kr[3] = to_tf32u(kv.w);
            float4 vv = *(const float4*)&g_qkv[base + 2 * C_DIM];
            uint32_t* vr = &Vs[row * 72 + dc];
            vr[0] = to_tf32u(vv.x); vr[1] = to_tf32u(vv.y);
            vr[2] = to_tf32u(vv.z); vr[3] = to_tf32u(vv.w);
        }
        __syncthreads();

        // S = Q.K^T : 32 q rows x 64 k cols per warp
        float sacc[2][8][4];
#pragma unroll
        for (int mt = 0; mt < 2; mt++)
#pragma unroll
            for (int j = 0; j < 8; j++)
#pragma unroll
                for (int c = 0; c < 4; c++) sacc[mt][j][c] = 0.f;

#pragma unroll
        for (int ds = 0; ds < 8; ds++) {
            const int d8 = ds * 8;
            uint32_t af[2][4];
#pragma unroll
            for (int mt = 0; mt < 2; mt++) {
                const uint32_t* base = &Qs[(qb + mt * 16) * 68 + d8];
                af[mt][0] = base[(g    ) * 68 + r    ];
                af[mt][1] = base[(g + 8) * 68 + r    ];
                af[mt][2] = base[(g    ) * 68 + r + 4];
                af[mt][3] = base[(g + 8) * 68 + r + 4];
            }
#pragma unroll
            for (int j = 0; j < 8; j++) {
                uint32_t bf[2];
                bf[0] = Ks[(8 * j + g) * 68 + d8 + r    ];
                bf[1] = Ks[(8 * j + g) * 68 + d8 + r + 4];
                MMA_TF32(sacc[0][j], af[0], bf);
                MMA_TF32(sacc[1][j], af[1], bf);
            }
        }

        // exp (max-free), accumulate l, stage P (own rows only)
#pragma unroll
        for (int mt = 0; mt < 2; mt++) {
#pragma unroll
            for (int j = 0; j < 8; j++) {
                float p0 = __expf(sacc[mt][j][0]);
                float p1 = __expf(sacc[mt][j][1]);
                float p2 = __expf(sacc[mt][j][2]);
                float p3 = __expf(sacc[mt][j][3]);
                lsum[mt][0] += p0 + p1;
                lsum[mt][1] += p2 + p3;
                const int col = 8 * j + 2 * r;
                uint32_t* pr0 = &Ps[(qb + mt * 16 + g    ) * 68 + col];
                uint32_t* pr1 = &Ps[(qb + mt * 16 + g + 8) * 68 + col];
                pr0[0] = to_tf32u(p0); pr0[1] = to_tf32u(p1);
                pr1[0] = to_tf32u(p2); pr1[1] = to_tf32u(p3);
            }
        }
        __syncwarp();   // P produced & consumed by this warp only

        // O += P.V (contraction over 64 k)
#pragma unroll
        for (int ks = 0; ks < 8; ks++) {
            const int k8 = ks * 8;
            uint32_t af[2][4];
#pragma unroll
            for (int mt = 0; mt < 2; mt++) {
                const uint32_t* base = &Ps[(qb + mt * 16) * 68 + k8];
                af[mt][0] = base[(g    ) * 68 + r    ];
                af[mt][1] = base[(g + 8) * 68 + r    ];
                af[mt][2] = base[(g    ) * 68 + r + 4];
                af[mt][3] = base[(g + 8) * 68 + r + 4];
            }
#pragma unroll
            for (int j = 0; j < 8; j++) {
                uint32_t bf[2];
                bf[0] = Vs[(k8 + r    ) * 72 + 8 * j + g];
                bf[1] = Vs[(k8 + r + 4) * 72 + 8 * j + g];
                MMA_TF32(oacc[0][j], af[0], bf);
                MMA_TF32(oacc[1][j], af[1], bf);
            }
        }
    }

    // Row sums: reduce across the quad (lanes sharing the same rows)
#pragma unroll
    for (int mt = 0; mt < 2; mt++)
#pragma unroll
        for (int rs = 0; rs < 2; rs++)
#pragma unroll
            for (int off = 1; off < 4; off <<= 1)
                lsum[mt][rs] += __shfl_xor_sync(0xffffffffu, lsum[mt][rs], off);

    // Store O / l in (h, q, t, d) layout
#pragma unroll
    for (int mt = 0; mt < 2; mt++) {
        const float inv0 = 1.f / lsum[mt][0];
        const float inv1 = 1.f / lsum[mt][1];
        const int qrow0 = q0 + qb + mt * 16 + g;
        float* o0 = &g_attn[((size_t)(h * HW_DIM + qrow0    ) * T_DIM + t) * HD];
        float* o1 = &g_attn[((size_t)(h * HW_DIM + qrow0 + 8) * T_DIM + t) * HD];
#pragma unroll
        for (int j = 0; j < 8; j++) {
            const int col = 8 * j + 2 * r;
            float2 v0; v0.x = oacc[mt][j][0] * inv0; v0.y = oacc[mt][j][1] * inv0;
            float2 v1; v1.x = oacc[mt][j][2] * inv1; v1.y = oacc[mt][j][3] * inv1;
            *(float2*)&o0[col] = v0;
            *(float2*)&o1[col] = v1;
        }
    }
}

// ---------------------------------------------------------------------------
// GEMM probe: one sample per block (64 blocks), k split over 256 threads.
// ---------------------------------------------------------------------------
__global__ __launch_bounds__(256) void probe_kernel(
    const float* __restrict__ A, const float* __restrict__ W,
    const float* __restrict__ bias, const float* __restrict__ Cout,
    int M, int N, int K, int* flag)
{
    __shared__ float red[256];
    const int p = blockIdx.x;
    const int m = (p * 6421 + 17) % M;
    const int n = (p * 3137 + 5) % N;
    float s = 0.f;
    for (int k = threadIdx.x; k < K; k += 256)
        s += A[(size_t)m * K + k] * W[(size_t)k * N + n];
    red[threadIdx.x] = s;
    __syncthreads();
    for (int off = 128; off; off >>= 1) {
        if (threadIdx.x < off) red[threadIdx.x] += red[threadIdx.x + off];
        __syncthreads();
    }
    if (threadIdx.x == 0) {
        float ref = red[0] + bias[n];
        float got = Cout[(size_t)m * N + n];
        float rel = fabsf(got - ref) / fmaxf(fabsf(ref), 0.05f);
        if (!(rel <= 0.02f)) atomicOr(flag, 1);   // NaN-safe
    }
}

// ---------------------------------------------------------------------------
// Attention probe: one sample per block (64 blocks), j split over 256 threads.
// ---------------------------------------------------------------------------
__global__ __launch_bounds__(256) void attn_probe_kernel(int* flag)
{
    __shared__ float rede[256], redv[256];
    const int p  = blockIdx.x;
    const int h  = p & 7;
    const int t  = (3 + 5 * p) & 15;
    const int qp = (97 * p + 11) & 1023;
    const int dp = (29 * p + 7) & 63;

    const float* qrow = &g_qkv[(size_t)(t * HW_DIM + qp) * QKV_N + h * HD];
    float se = 0.f, sv = 0.f;
    for (int j = threadIdx.x; j < HW_DIM; j += 256) {
        const float* base = &g_qkv[(size_t)(t * HW_DIM + j) * QKV_N + h * HD];
        float s = 0.f;
#pragma unroll
        for (int d = 0; d < 64; d++) s += qrow[d] * base[C_DIM + d];
        float e = __expf(s * 0.125f);
        se += e;
        sv += e * base[2 * C_DIM + dp];
    }
    rede[threadIdx.x] = se;
    redv[threadIdx.x] = sv;
    __syncthreads();
    for (int off = 128; off; off >>= 1) {
        if (threadIdx.x < off) {
            rede[threadIdx.x] += rede[threadIdx.x + off];
            redv[threadIdx.x] += redv[threadIdx.x + off];
        }
        __syncthreads();
    }
    if (threadIdx.x == 0) {
        float ref = redv[0] / rede[0];
        float got = g_attn[((size_t)(h * HW_DIM + qp) * T_DIM + t) * HD + dp];
        float rel = fabsf(got - ref) / fmaxf(fabsf(ref), 0.002f);
        if (!(rel <= 0.05f)) atomicOr(flag, 1);   // NaN-safe
    }
}

// ---------------------------------------------------------------------------
// Fixup GEMM (proven SIMT, round-2): runs ONLY if *flag != 0.
// ---------------------------------------------------------------------------
__global__ __launch_bounds__(256) void gemm_bias_fix_kernel(
    const float* __restrict__ A, const float* __restrict__ B,
    const float* __restrict__ bias, float* __restrict__ Cmat,
    int M, int N, int K, const int* __restrict__ flag)
{
    if (*(volatile const int*)flag == 0) return;

    constexpr int BM = 128, BN = 128, BK = 16;
    __shared__ float As[BK][BM + 4];
    __shared__ float Bs[BK][BN + 4];

    const int tid = threadIdx.x;
    const int tx = tid & 15;
    const int ty = tid >> 4;
    const int m0 = blockIdx.y * BM;
    const int n0 = blockIdx.x * BN;

    const int aRow0 = (tid      ) >> 2;
    const int aRow1 = (tid + 256) >> 2;
    const int aKq0  = (tid & 3) << 2;
    const int bKr0  = (tid      ) >> 5;
    const int bKr1  = (tid + 256) >> 5;
    const int bN4   = (tid & 31) << 2;

    float4 aReg[2], bReg[2];
    aReg[0] = *(const float4*)&A[(size_t)(m0 + aRow0) * K + aKq0];
    aReg[1] = *(const float4*)&A[(size_t)(m0 + aRow1) * K + aKq0];
    bReg[0] = *(const float4*)&B[(size_t)bKr0 * N + n0 + bN4];
    bReg[1] = *(const float4*)&B[(size_t)bKr1 * N + n0 + bN4];

    float acc[8][8];
#pragma unroll
    for (int r = 0; r < 8; r++)
#pragma unroll
        for (int c = 0; c < 8; c++) acc[r][c] = 0.f;

    for (int k0 = 0; k0 < K; k0 += BK) {
        As[aKq0 + 0][aRow0] = aReg[0].x;
        As[aKq0 + 1][aRow0] = aReg[0].y;
        As[aKq0 + 2][aRow0] = aReg[0].z;
        As[aKq0 + 3][aRow0] = aReg[0].w;
        As[aKq0 + 0][aRow1] = aReg[1].x;
        As[aKq0 + 1][aRow1] = aReg[1].y;
        As[aKq0 + 2][aRow1] = aReg[1].z;
        As[aKq0 + 3][aRow1] = aReg[1].w;
        *(float4*)&Bs[bKr0][bN4] = bReg[0];
        *(float4*)&Bs[bKr1][bN4] = bReg[1];
        __syncthreads();

        if (k0 + BK < K) {
            int kn = k0 + BK;
            aReg[0] = *(const float4*)&A[(size_t)(m0 + aRow0) * K + kn + aKq0];
            aReg[1] = *(const float4*)&A[(size_t)(m0 + aRow1) * K + kn + aKq0];
            bReg[0] = *(const float4*)&B[(size_t)(kn + bKr0) * N + n0 + bN4];
            bReg[1] = *(const float4*)&B[(size_t)(kn + bKr1) * N + n0 + bN4];
        }

#pragma unroll
        for (int kk = 0; kk < BK; kk++) {
            float a[8], b[8];
            float4 a0 = *(const float4*)&As[kk][ty * 8];
            float4 a1 = *(const float4*)&As[kk][ty * 8 + 4];
            float4 b0 = *(const float4*)&Bs[kk][tx * 8];
            float4 b1 = *(const float4*)&Bs[kk][tx * 8 + 4];
            a[0]=a0.x; a[1]=a0.y; a[2]=a0.z; a[3]=a0.w;
            a[4]=a1.x; a[5]=a1.y; a[6]=a1.z; a[7]=a1.w;
            b[0]=b0.x; b[1]=b0.y; b[2]=b0.z; b[3]=b0.w;
            b[4]=b1.x; b[5]=b1.y; b[6]=b1.z; b[7]=b1.w;
#pragma unroll
            for (int r = 0; r < 8; r++)
#pragma unroll
                for (int c = 0; c < 8; c++)
                    acc[r][c] += a[r] * b[c];
        }
        __syncthreads();
    }

    float bb[8];
#pragma unroll
    for (int c = 0; c < 8; c++) bb[c] = bias[n0 + tx * 8 + c];
#pragma unroll
    for (int r = 0; r < 8; r++) {
        int m = m0 + ty * 8 + r;
#pragma unroll
        for (int c = 0; c < 8; c += 4) {
            float4 v;
            v.x = acc[r][c + 0] + bb[c + 0];
            v.y = acc[r][c + 1] + bb[c + 1];
            v.z = acc[r][c + 2] + bb[c + 2];
            v.w = acc[r][c + 3] + bb[c + 3];
            *(float4*)&Cmat[(size_t)m * N + n0 + tx * 8 + c] = v;
        }
    }
}

// ---------------------------------------------------------------------------
// Fixup attention (proven SIMT, round-2): runs ONLY if *flag != 0.
// ---------------------------------------------------------------------------
#define LDT 68

__global__ __launch_bounds__(256) void attn_fix_kernel(const int* __restrict__ flag)
{
    if (*(volatile const int*)flag == 0) return;

    extern __shared__ float sm[];
    float* Qt = sm;
    float* Kt = Qt + 64 * LDT;
    float* Vss = Kt + 64 * LDT;
    float* Pss = Vss + 64 * LDT;

    const int tid = threadIdx.x;
    const int tx = tid & 15;
    const int ty = tid >> 4;
    const int pair = blockIdx.y;
    const int h = pair >> 4;
    const int t = pair & 15;
    const int q0 = blockIdx.x * 64;

#pragma unroll
    for (int i = 0; i < 16; i++) {
        int idx = tid + 256 * i;
        int q = idx >> 6;
        int d = idx & 63;
        Qt[d * LDT + q] =
            g_qkv[(size_t)(t * HW_DIM + q0 + q) * QKV_N + h * HD + d] * 0.125f;
    }

    float mrow[4], lrow[4];
#pragma unroll
    for (int r = 0; r < 4; r++) { mrow[r] = -CUDART_INF_F; lrow[r] = 0.f; }

    float o[4][4];
#pragma unroll
    for (int r = 0; r < 4; r++)
#pragma unroll
        for (int c = 0; c < 4; c++) o[r][c] = 0.f;

    for (int k0 = 0; k0 < HW_DIM; k0 += 64) {
        __syncthreads();
#pragma unroll
        for (int i = 0; i < 16; i++) {
            int idx = tid + 256 * i;
            int kk = idx >> 6;
            int d  = idx & 63;
            size_t base = (size_t)(t * HW_DIM + k0 + kk) * QKV_N + h * HD + d;
            Kt[d * LDT + kk] = g_qkv[base + C_DIM];
            Vss[kk * LDT + d] = g_qkv[base + 2 * C_DIM];
        }
        __syncthreads();

        float s[4][4];
#pragma unroll
        for (int r = 0; r < 4; r++)
#pragma unroll
            for (int c = 0; c < 4; c++) s[r][c] = 0.f;
#pragma unroll
        for (int d = 0; d < 64; d++) {
            float4 a = *(const float4*)&Qt[d * LDT + 4 * ty];
            float4 b = *(const float4*)&Kt[d * LDT + 4 * tx];
            s[0][0] += a.x*b.x; s[0][1] += a.x*b.y; s[0][2] += a.x*b.z; s[0][3] += a.x*b.w;
            s[1][0] += a.y*b.x; s[1][1] += a.y*b.y; s[1][2] += a.y*b.z; s[1][3] += a.y*b.w;
            s[2][0] += a.z*b.x; s[2][1] += a.z*b.y; s[2][2] += a.z*b.z; s[2][3] += a.z*b.w;
            s[3][0] += a.w*b.x; s[3][1] += a.w*b.y; s[3][2] += a.w*b.z; s[3][3] += a.w*b.w;
        }

#pragma unroll
        for (int r = 0; r < 4; r++) {
            float lm = fmaxf(fmaxf(s[r][0], s[r][1]), fmaxf(s[r][2], s[r][3]));
#pragma unroll
            for (int off = 8; off; off >>= 1)
                lm = fmaxf(lm, __shfl_xor_sync(0xffffffffu, lm, off, 16));
            float mn = fmaxf(mrow[r], lm);
            float alpha = __expf(mrow[r] - mn);
            mrow[r] = mn;

            float rs = 0.f;
#pragma unroll
            for (int c = 0; c < 4; c++) {
                float p = __expf(s[r][c] - mn);
                s[r][c] = p;
                rs += p;
            }
#pragma unroll
            for (int off = 8; off; off >>= 1)
                rs += __shfl_xor_sync(0xffffffffu, rs, off, 16);
            lrow[r] = lrow[r] * alpha + rs;

            int qi = 4 * ty + r;
            float4 pv; pv.x = s[r][0]; pv.y = s[r][1]; pv.z = s[r][2]; pv.w = s[r][3];
            *(float4*)&Pss[qi * LDT + 4 * tx] = pv;
#pragma unroll
            for (int c = 0; c < 4; c++) o[r][c] *= alpha;
        }
        __syncwarp();

#pragma unroll
        for (int kk = 0; kk < 64; kk += 4) {
            float4 pr[4];
#pragma unroll
            for (int r = 0; r < 4; r++)
                pr[r] = *(const float4*)&Pss[(4 * ty + r) * LDT + kk];

            float4 v;
            v = *(const float4*)&Vss[(kk + 0) * LDT + 4 * tx];
            o[0][0]+=pr[0].x*v.x; o[0][1]+=pr[0].x*v.y; o[0][2]+=pr[0].x*v.z; o[0][3]+=pr[0].x*v.w;
            o[1][0]+=pr[1].x*v.x; o[1][1]+=pr[1].x*v.y; o[1][2]+=pr[1].x*v.z; o[1][3]+=pr[1].x*v.w;
            o[2][0]+=pr[2].x*v.x; o[2][1]+=pr[2].x*v.y; o[2][2]+=pr[2].x*v.z; o[2][3]+=pr[2].x*v.w;
            o[3][0]+=pr[3].x*v.x; o[3][1]+=pr[3].x*v.y; o[3][2]+=pr[3].x*v.z; o[3][3]+=pr[3].x*v.w;
            v = *(const float4*)&Vss[(kk + 1) * LDT + 4 * tx];
            o[0][0]+=pr[0].y*v.x; o[0][1]+=pr[0].y*v.y; o[0][2]+=pr[0].y*v.z; o[0][3]+=pr[0].y*v.w;
            o[1][0]+=pr[1].y*v.x; o[1][1]+=pr[1].y*v.y; o[1][2]+=pr[1].y*v.z; o[1][3]+=pr[1].y*v.w;
            o[2][0]+=pr[2].y*v.x; o[2][1]+=pr[2].y*v.y; o[2][2]+=pr[2].y*v.z; o[2][3]+=pr[2].y*v.w;
            o[3][0]+=pr[3].y*v.x; o[3][1]+=pr[3].y*v.y; o[3][2]+=pr[3].y*v.z; o[3][3]+=pr[3].y*v.w;
            v = *(const float4*)&Vss[(kk + 2) * LDT + 4 * tx];
            o[0][0]+=pr[0].z*v.x; o[0][1]+=pr[0].z*v.y; o[0][2]+=pr[0].z*v.z; o[0][3]+=pr[0].z*v.w;
            o[1][0]+=pr[1].z*v.x; o[1][1]+=pr[1].z*v.y; o[1][2]+=pr[1].z*v.z; o[1][3]+=pr[1].z*v.w;
            o[2][0]+=pr[2].z*v.x; o[2][1]+=pr[2].z*v.y; o[2][2]+=pr[2].z*v.z; o[2][3]+=pr[2].z*v.w;
            o[3][0]+=pr[3].z*v.x; o[3][1]+=pr[3].z*v.y; o[3][2]+=pr[3].z*v.z; o[3][3]+=pr[3].z*v.w;
            v = *(const float4*)&Vss[(kk + 3) * LDT + 4 * tx];
            o[0][0]+=pr[0].w*v.x; o[0][1]+=pr[0].w*v.y; o[0][2]+=pr[0].w*v.z; o[0][3]+=pr[0].w*v.w;
            o[1][0]+=pr[1].w*v.x; o[1][1]+=pr[1].w*v.y; o[1][2]+=pr[1].w*v.z; o[1][3]+=pr[1].w*v.w;
            o[2][0]+=pr[2].w*v.x; o[2][1]+=pr[2].w*v.y; o[2][2]+=pr[2].w*v.z; o[2][3]+=pr[2].w*v.w;
            o[3][0]+=pr[3].w*v.x; o[3][1]+=pr[3].w*v.y; o[3][2]+=pr[3].w*v.z; o[3][3]+=pr[3].w*v.w;
        }
    }

#pragma unroll
    for (int r = 0; r < 4; r++) {
        int qi = 4 * ty + r;
        float inv = 1.f / lrow[r];
        float4 v;
        v.x = o[r][0] * inv;
        v.y = o[r][1] * inv;
        v.z = o[r][2] * inv;
        v.w = o[r][3] * inv;
        size_t idx = ((size_t)(h * HW_DIM + q0 + qi) * T_DIM + t) * HD + 4 * tx;
        *(float4*)&g_attn[idx] = v;
    }
}

// ---------------------------------------------------------------------------

extern "C" void kernel_launch(void* const* d_in, const int* in_sizes, int n_in,
                              void* d_out, int out_size)
{
    (void)in_sizes; (void)n_in; (void)out_size;
    const float* x    = (const float*)d_in[0];
    const float* Wqkv = (const float*)d_in[1];
    const float* bqkv = (const float*)d_in[2];
    const float* Wout = (const float*)d_in[3];
    const float* bout = (const float*)d_in[4];
    float* out = (float*)d_out;

    float* qkv_ptr  = nullptr;
    float* attn_ptr = nullptr;
    int*   bad_ptr  = nullptr;
    cudaGetSymbolAddress((void**)&qkv_ptr,  g_qkv);
    cudaGetSymbolAddress((void**)&attn_ptr, g_attn);
    cudaGetSymbolAddress((void**)&bad_ptr,  g_bad);

    cudaFuncSetAttribute(mma_gemm_kernel,
                         cudaFuncAttributeMaxDynamicSharedMemorySize, GEMM_SMEM_BYTES);
    cudaFuncSetAttribute(mma_attn_kernel,
                         cudaFuncAttributeMaxDynamicSharedMemorySize, ATTN_SMEM_BYTES);
    const int fix_smem = (int)((size_t)(4 * 64 * LDT) * sizeof(float));
    cudaFuncSetAttribute(attn_fix_kernel,
                         cudaFuncAttributeMaxDynamicSharedMemorySize, fix_smem);

    // Zero probe flags (async memset is graph-capturable)
    cudaMemsetAsync(bad_ptr, 0, 4 * sizeof(int));

    // 1) QKV projection (mma.sync tf32) + probe + conditional SIMT repair
    {
        dim3 grid(QKV_N / 128, M_ROWS / 128);
        mma_gemm_kernel<<<grid, 256, GEMM_SMEM_BYTES>>>(x, Wqkv, bqkv, qkv_ptr,
                                                        M_ROWS, QKV_N, C_DIM);
        probe_kernel<<<64, 256>>>(x, Wqkv, bqkv, qkv_ptr,
                                  M_ROWS, QKV_N, C_DIM, bad_ptr);
        gemm_bias_fix_kernel<<<grid, 256>>>(x, Wqkv, bqkv, qkv_ptr,
                                            M_ROWS, QKV_N, C_DIM, bad_ptr);
    }

    // 2) Attention (mma.sync tf32, 4-warp / 2-m-tile) + probe + conditional repair
    {
        dim3 grid(HW_DIM / 128, NH * T_DIM);
        mma_attn_kernel<<<grid, 128, ATTN_SMEM_BYTES>>>();
        attn_probe_kernel<<<64, 256>>>(bad_ptr + 2);
        dim3 fgrid(HW_DIM / 64, NH * T_DIM);
        attn_fix_kernel<<<fgrid, 256, fix_smem>>>(bad_ptr + 2);
    }

    // 3) Output projection (mma.sync tf32) + probe + conditional SIMT repair
    {
        dim3 grid(C_DIM / 128, M_ROWS / 128);
        mma_gemm_kernel<<<grid, 256, GEMM_SMEM_BYTES>>>(attn_ptr, Wout, bout, out,
                                                        M_ROWS, C_DIM, C_DIM);
        probe_kernel<<<64, 256>>>(attn_ptr, Wout, bout, out,
                                  M_ROWS, C_DIM, C_DIM, bad_ptr + 1);
        gemm_bias_fix_kernel<<<grid, 256>>>(attn_ptr, Wout, bout, out,
                                            M_ROWS, C_DIM, C_DIM, bad_ptr + 1);
    }
}

// round 12
// speedup vs baseline: 1.0357x; 1.0357x over previous
#include <cuda_runtime.h>
#include <math_constants.h>
#include <cstdint>
#include <cstddef>

#define T_DIM 16
#define HW_DIM 1024
#define C_DIM 512
#define NH 8
#define HD 64
#define M_ROWS (T_DIM * HW_DIM)   /* 16384 */
#define QKV_N (3 * C_DIM)         /* 1536  */

// Scratch (device globals; no allocation allowed)
__device__ float g_qkv[M_ROWS * QKV_N];     // ~100.7 MB
__device__ float g_attn[M_ROWS * C_DIM];    // ~33.6 MB
__device__ int   g_bad[4];                  // probe verdicts

// ---------------------------------------------------------------------------
// Helpers (arch-agnostic PTX only: tf32 cvt + mma.sync + cp.async, sm_80+)
// ---------------------------------------------------------------------------
__device__ __forceinline__ uint32_t to_tf32u(float x) {
    float r; asm("cvt.rna.tf32.f32 %0, %1;" : "=f"(r) : "f"(x));
    return __float_as_uint(r);
}
__device__ __forceinline__ uint32_t smem_u32(const void* p) {
    uint32_t a;
    asm("{ .reg .u64 t; cvta.to.shared.u64 t, %1; cvt.u32.u64 %0, t; }" : "=r"(a) : "l"(p));
    return a;
}
__device__ __forceinline__ void cp_async16(uint32_t saddr, const void* gptr) {
    asm volatile("cp.async.cg.shared.global [%0], [%1], 16;" :: "r"(saddr), "l"(gptr) : "memory");
}
#define CP_COMMIT() asm volatile("cp.async.commit_group;" ::: "memory")
#define CP_WAIT1()  asm volatile("cp.async.wait_group 1;" ::: "memory")
#define CP_WAIT0()  asm volatile("cp.async.wait_group 0;" ::: "memory")

// D += A(16x8,row) * B(8x8,col); tf32 inputs as b32 regs, f32 accum.
#define MMA_TF32(d, a, b)                                                      \
    asm volatile("mma.sync.aligned.m16n8k8.row.col.f32.tf32.tf32.f32 "         \
        "{%0,%1,%2,%3}, {%4,%5,%6,%7}, {%8,%9}, {%0,%1,%2,%3};"                \
        : "+f"((d)[0]), "+f"((d)[1]), "+f"((d)[2]), "+f"((d)[3])               \
        : "r"((a)[0]), "r"((a)[1]), "r"((a)[2]), "r"((a)[3]),                  \
          "r"((b)[0]), "r"((b)[1]))

// ---------------------------------------------------------------------------
// mma.sync tf32 GEMM (unchanged from R9 WIN): out = A@B + bias
// ---------------------------------------------------------------------------
#define GEMM_SMEM_BYTES ((2 * 128 * 36 + 2 * 32 * 136) * 4)   /* 71680 */

__global__ __launch_bounds__(256) void mma_gemm_kernel(
    const float* __restrict__ A, const float* __restrict__ B,
    const float* __restrict__ bias, float* __restrict__ out,
    int M, int N, int K)
{
    extern __shared__ uint32_t smu[];
    uint32_t* As[2] = { smu, smu + 128 * 36 };
    uint32_t* Bs[2] = { smu + 2 * 128 * 36, smu + 2 * 128 * 36 + 32 * 136 };

    const int tid  = threadIdx.x;
    const int wid  = tid >> 5;
    const int lane = tid & 31;
    const int g    = lane >> 2;
    const int r    = lane & 3;
    const int wm   = (wid & 3) * 32;
    const int wn   = (wid >> 2) * 64;
    const int m0   = blockIdx.y * 128;
    const int n0   = blockIdx.x * 128;

    const int aRow = tid >> 3;
    const int aKc  = (tid & 7) << 2;
    const int bKr  = tid >> 5;
    const int bNc  = (tid & 31) << 2;

    float4 pa[4], pb[4];
#pragma unroll
    for (int i = 0; i < 4; i++) {
        pa[i] = *(const float4*)&A[(size_t)(m0 + aRow + 32 * i) * K + aKc];
        pb[i] = *(const float4*)&B[(size_t)(bKr + 8 * i) * N + n0 + bNc];
    }

    float acc[2][8][4];
#pragma unroll
    for (int mt = 0; mt < 2; mt++)
#pragma unroll
        for (int j = 0; j < 8; j++)
#pragma unroll
            for (int c = 0; c < 4; c++) acc[mt][j][c] = 0.f;

    const int NS = K / 32;
    for (int s = 0; s < NS; s++) {
        const int b = s & 1;
#pragma unroll
        for (int i = 0; i < 4; i++) {
            uint32_t* ar = &As[b][(aRow + 32 * i) * 36 + aKc];
            ar[0] = to_tf32u(pa[i].x); ar[1] = to_tf32u(pa[i].y);
            ar[2] = to_tf32u(pa[i].z); ar[3] = to_tf32u(pa[i].w);
            uint32_t* br = &Bs[b][(bKr + 8 * i) * 136 + bNc];
            br[0] = to_tf32u(pb[i].x); br[1] = to_tf32u(pb[i].y);
            br[2] = to_tf32u(pb[i].z); br[3] = to_tf32u(pb[i].w);
        }
        __syncthreads();

        if (s + 1 < NS) {
            const int kn = (s + 1) * 32;
#pragma unroll
            for (int i = 0; i < 4; i++) {
                pa[i] = *(const float4*)&A[(size_t)(m0 + aRow + 32 * i) * K + kn + aKc];
                pb[i] = *(const float4*)&B[(size_t)(kn + bKr + 8 * i) * N + n0 + bNc];
            }
        }

#pragma unroll
        for (int ks = 0; ks < 4; ks++) {
            const int k8 = ks * 8;
            uint32_t af[2][4];
#pragma unroll
            for (int mt = 0; mt < 2; mt++) {
                const uint32_t* base = &As[b][(wm + mt * 16) * 36 + k8];
                af[mt][0] = base[(g    ) * 36 + r    ];
                af[mt][1] = base[(g + 8) * 36 + r    ];
                af[mt][2] = base[(g    ) * 36 + r + 4];
                af[mt][3] = base[(g + 8) * 36 + r + 4];
            }
#pragma unroll
            for (int j = 0; j < 8; j++) {
                uint32_t bf[2];
                const uint32_t* base = &Bs[b][k8 * 136 + wn + 8 * j + g];
                bf[0] = base[r * 136];
                bf[1] = base[(r + 4) * 136];
                MMA_TF32(acc[0][j], af[0], bf);
                MMA_TF32(acc[1][j], af[1], bf);
            }
        }
        __syncthreads();
    }

#pragma unroll
    for (int mt = 0; mt < 2; mt++) {
        const int row = m0 + wm + mt * 16 + g;
#pragma unroll
        for (int j = 0; j < 8; j++) {
            const int col = n0 + wn + 8 * j + 2 * r;
            const float b0 = bias[col], b1 = bias[col + 1];
            float2 v0; v0.x = acc[mt][j][0] + b0; v0.y = acc[mt][j][1] + b1;
            float2 v1; v1.x = acc[mt][j][2] + b0; v1.y = acc[mt][j][3] + b1;
            *(float2*)&out[(size_t)row * N + col]       = v0;
            *(float2*)&out[(size_t)(row + 8) * N + col] = v1;
        }
    }
}

// ---------------------------------------------------------------------------
// mma.sync tf32 attention v4: R9's proven 8-warp/16-q-row mapping + cp.async
// double-buffered K/V staging (chunk = 32 k-rows, 32 chunks). tf32 cvt moved
// to fragment load (each element converted exactly once, as before). Smem
// 89.1KB + __launch_bounds__(256,2) => 2 CTAs/SM by both smem and regfile.
// Max-free softmax (scores O(1); probe+fixup backstops). Output (h, q, t, d).
// ---------------------------------------------------------------------------
#define AQS_OFF 0                          /* Qs: 128x68 tf32             */
#define AKS_OFF (128 * 68)                 /* Ks[2]: 32x68 fp32 each      */
#define AVS_OFF (AKS_OFF + 2 * 32 * 68)    /* Vs[2]: 32x72 fp32 each      */
#define APS_OFF (AVS_OFF + 2 * 32 * 72)    /* Ps: 128x36 tf32             */
#define ATTN_SMEM_BYTES ((APS_OFF + 128 * 36) * 4)   /* 89088 */

__global__ void __launch_bounds__(256, 2) mma_attn_kernel()
{
    extern __shared__ uint32_t smu[];
    uint32_t* Qs  = smu + AQS_OFF;
    float*    Ksf = (float*)(smu + AKS_OFF);
    float*    Vsf = (float*)(smu + AVS_OFF);
    uint32_t* Ps  = smu + APS_OFF;

    const int tid  = threadIdx.x;
    const int wid  = tid >> 5;
    const int lane = tid & 31;
    const int g    = lane >> 2;
    const int r    = lane & 3;
    const int pair = blockIdx.y;
    const int h    = pair >> 4;
    const int t    = pair & 15;
    const int q0   = blockIdx.x * 128;
    const int qb   = wid * 16;

    const uint32_t ks_base = smem_u32(Ksf);
    const uint32_t vs_base = smem_u32(Vsf);

    // Issue one 32-row K/V chunk into buffer b (4 cp.async / thread)
    auto issue_chunk = [&](int kc, int b) {
#pragma unroll
        for (int i = 0; i < 2; i++) {
            int idx = tid + 256 * i;       // 0..511
            int row = idx >> 4;            // 0..31
            int dc  = (idx & 15) << 2;
            const float* ksrc = &g_qkv[(size_t)(t * HW_DIM + kc * 32 + row) * QKV_N
                                       + C_DIM + h * HD + dc];
            cp_async16(ks_base + (uint32_t)(b * 32 * 68 + row * 68 + dc) * 4, ksrc);
            cp_async16(vs_base + (uint32_t)(b * 32 * 72 + row * 72 + dc) * 4,
                       ksrc + C_DIM);
        }
    };

    // Kick off chunks 0 and 1 immediately (overlap with Q staging below)
    issue_chunk(0, 0); CP_COMMIT();
    issue_chunk(1, 1); CP_COMMIT();

    // Stage Q (scaled 1/8, tf32): 128 x 64
#pragma unroll
    for (int i = 0; i < 8; i++) {
        int idx = tid + 256 * i;
        int row = idx >> 4;
        int dc  = (idx & 15) << 2;
        float4 v = *(const float4*)&g_qkv[(size_t)(t * HW_DIM + q0 + row) * QKV_N
                                          + h * HD + dc];
        uint32_t* qr = &Qs[row * 68 + dc];
        qr[0] = to_tf32u(v.x * 0.125f); qr[1] = to_tf32u(v.y * 0.125f);
        qr[2] = to_tf32u(v.z * 0.125f); qr[3] = to_tf32u(v.w * 0.125f);
    }

    float oacc[8][4];
#pragma unroll
    for (int j = 0; j < 8; j++)
#pragma unroll
        for (int c = 0; c < 4; c++) oacc[j][c] = 0.f;
    float lsum0 = 0.f, lsum1 = 0.f;

    for (int kc = 0; kc < 32; kc++) {
        const int b = kc & 1;
        if (kc < 31) CP_WAIT1(); else CP_WAIT0();   // chunk kc's copies landed
        __syncthreads();                            // visible block-wide (+ Q on kc=0)

        const float* Kc = Ksf + b * 32 * 68;
        const float* Vc = Vsf + b * 32 * 72;

        // S = Q.K^T : 16 q rows x 32 k cols (K cvt at fragment load)
        float sacc[4][4];
#pragma unroll
        for (int j = 0; j < 4; j++)
#pragma unroll
            for (int c = 0; c < 4; c++) sacc[j][c] = 0.f;

#pragma unroll
        for (int ds = 0; ds < 8; ds++) {
            const int d8 = ds * 8;
            uint32_t af[4];
            af[0] = Qs[(qb + g    ) * 68 + d8 + r    ];
            af[1] = Qs[(qb + g + 8) * 68 + d8 + r    ];
            af[2] = Qs[(qb + g    ) * 68 + d8 + r + 4];
            af[3] = Qs[(qb + g + 8) * 68 + d8 + r + 4];
#pragma unroll
            for (int j = 0; j < 4; j++) {
                uint32_t bf[2];
                bf[0] = to_tf32u(Kc[(8 * j + g) * 68 + d8 + r    ]);
                bf[1] = to_tf32u(Kc[(8 * j + g) * 68 + d8 + r + 4]);
                MMA_TF32(sacc[j], af, bf);
            }
        }

        // exp (max-free), accumulate l, stage P (own rows only)
#pragma unroll
        for (int j = 0; j < 4; j++) {
            float p0 = __expf(sacc[j][0]);
            float p1 = __expf(sacc[j][1]);
            float p2 = __expf(sacc[j][2]);
            float p3 = __expf(sacc[j][3]);
            lsum0 += p0 + p1;
            lsum1 += p2 + p3;
            const int col = 8 * j + 2 * r;
            uint32_t* pr0 = &Ps[(qb + g    ) * 36 + col];
            uint32_t* pr1 = &Ps[(qb + g + 8) * 36 + col];
            pr0[0] = to_tf32u(p0); pr0[1] = to_tf32u(p1);
            pr1[0] = to_tf32u(p2); pr1[1] = to_tf32u(p3);
        }
        __syncwarp();   // P produced & consumed by this warp only

        // O += P.V : contraction 32 k (4 k8 steps), 64 d cols (8 j)
#pragma unroll
        for (int ks = 0; ks < 4; ks++) {
            const int k8 = ks * 8;
            uint32_t af[4];
            af[0] = Ps[(qb + g    ) * 36 + k8 + r    ];
            af[1] = Ps[(qb + g + 8) * 36 + k8 + r    ];
            af[2] = Ps[(qb + g    ) * 36 + k8 + r + 4];
            af[3] = Ps[(qb + g + 8) * 36 + k8 + r + 4];
#pragma unroll
            for (int j = 0; j < 8; j++) {
                uint32_t bf[2];
                bf[0] = to_tf32u(Vc[(k8 + r    ) * 72 + 8 * j + g]);
                bf[1] = to_tf32u(Vc[(k8 + r + 4) * 72 + 8 * j + g]);
                MMA_TF32(oacc[j], af, bf);
            }
        }
        __syncthreads();   // all reads of buffer b complete
        if (kc + 2 < 32) { issue_chunk(kc + 2, b); CP_COMMIT(); }
    }

    // Row sums: reduce across the quad (lanes sharing the same rows)
#pragma unroll
    for (int off = 1; off < 4; off <<= 1) {
        lsum0 += __shfl_xor_sync(0xffffffffu, lsum0, off);
        lsum1 += __shfl_xor_sync(0xffffffffu, lsum1, off);
    }
    const float inv0 = 1.f / lsum0;
    const float inv1 = 1.f / lsum1;

    // Store O / l in (h, q, t, d) layout (reshape bug preserved)
    const int qrow0 = q0 + qb + g;
    float* o0 = &g_attn[((size_t)(h * HW_DIM + qrow0    ) * T_DIM + t) * HD];
    float* o1 = &g_attn[((size_t)(h * HW_DIM + qrow0 + 8) * T_DIM + t) * HD];
#pragma unroll
    for (int j = 0; j < 8; j++) {
        const int col = 8 * j + 2 * r;
        float2 v0; v0.x = oacc[j][0] * inv0; v0.y = oacc[j][1] * inv0;
        float2 v1; v1.x = oacc[j][2] * inv1; v1.y = oacc[j][3] * inv1;
        *(float2*)&o0[col] = v0;
        *(float2*)&o1[col] = v1;
    }
}

// ---------------------------------------------------------------------------
// GEMM probe: one sample per block (64 blocks), k split over 256 threads.
// ---------------------------------------------------------------------------
__global__ __launch_bounds__(256) void probe_kernel(
    const float* __restrict__ A, const float* __restrict__ W,
    const float* __restrict__ bias, const float* __restrict__ Cout,
    int M, int N, int K, int* flag)
{
    __shared__ float red[256];
    const int p = blockIdx.x;
    const int m = (p * 6421 + 17) % M;
    const int n = (p * 3137 + 5) % N;
    float s = 0.f;
    for (int k = threadIdx.x; k < K; k += 256)
        s += A[(size_t)m * K + k] * W[(size_t)k * N + n];
    red[threadIdx.x] = s;
    __syncthreads();
    for (int off = 128; off; off >>= 1) {
        if (threadIdx.x < off) red[threadIdx.x] += red[threadIdx.x + off];
        __syncthreads();
    }
    if (threadIdx.x == 0) {
        float ref = red[0] + bias[n];
        float got = Cout[(size_t)m * N + n];
        float rel = fabsf(got - ref) / fmaxf(fabsf(ref), 0.05f);
        if (!(rel <= 0.02f)) atomicOr(flag, 1);   // NaN-safe
    }
}

// ---------------------------------------------------------------------------
// Attention probe: one sample per block (64 blocks), j split over 256 threads.
// ---------------------------------------------------------------------------
__global__ __launch_bounds__(256) void attn_probe_kernel(int* flag)
{
    __shared__ float rede[256], redv[256];
    const int p  = blockIdx.x;
    const int h  = p & 7;
    const int t  = (3 + 5 * p) & 15;
    const int qp = (97 * p + 11) & 1023;
    const int dp = (29 * p + 7) & 63;

    const float* qrow = &g_qkv[(size_t)(t * HW_DIM + qp) * QKV_N + h * HD];
    float se = 0.f, sv = 0.f;
    for (int j = threadIdx.x; j < HW_DIM; j += 256) {
        const float* base = &g_qkv[(size_t)(t * HW_DIM + j) * QKV_N + h * HD];
        float s = 0.f;
#pragma unroll
        for (int d = 0; d < 64; d++) s += qrow[d] * base[C_DIM + d];
        float e = __expf(s * 0.125f);
        se += e;
        sv += e * base[2 * C_DIM + dp];
    }
    rede[threadIdx.x] = se;
    redv[threadIdx.x] = sv;
    __syncthreads();
    for (int off = 128; off; off >>= 1) {
        if (threadIdx.x < off) {
            rede[threadIdx.x] += rede[threadIdx.x + off];
            redv[threadIdx.x] += redv[threadIdx.x + off];
        }
        __syncthreads();
    }
    if (threadIdx.x == 0) {
        float ref = redv[0] / rede[0];
        float got = g_attn[((size_t)(h * HW_DIM + qp) * T_DIM + t) * HD + dp];
        float rel = fabsf(got - ref) / fmaxf(fabsf(ref), 0.002f);
        if (!(rel <= 0.05f)) atomicOr(flag, 1);   // NaN-safe
    }
}

// ---------------------------------------------------------------------------
// Fixup GEMM (proven SIMT, round-2): runs ONLY if *flag != 0.
// ---------------------------------------------------------------------------
__global__ __launch_bounds__(256) void gemm_bias_fix_kernel(
    const float* __restrict__ A, const float* __restrict__ B,
    const float* __restrict__ bias, float* __restrict__ Cmat,
    int M, int N, int K, const int* __restrict__ flag)
{
    if (*(volatile const int*)flag == 0) return;

    constexpr int BM = 128, BN = 128, BK = 16;
    __shared__ float As[BK][BM + 4];
    __shared__ float Bs[BK][BN + 4];

    const int tid = threadIdx.x;
    const int tx = tid & 15;
    const int ty = tid >> 4;
    const int m0 = blockIdx.y * BM;
    const int n0 = blockIdx.x * BN;

    const int aRow0 = (tid      ) >> 2;
    const int aRow1 = (tid + 256) >> 2;
    const int aKq0  = (tid & 3) << 2;
    const int bKr0  = (tid      ) >> 5;
    const int bKr1  = (tid + 256) >> 5;
    const int bN4   = (tid & 31) << 2;

    float4 aReg[2], bReg[2];
    aReg[0] = *(const float4*)&A[(size_t)(m0 + aRow0) * K + aKq0];
    aReg[1] = *(const float4*)&A[(size_t)(m0 + aRow1) * K + aKq0];
    bReg[0] = *(const float4*)&B[(size_t)bKr0 * N + n0 + bN4];
    bReg[1] = *(const float4*)&B[(size_t)bKr1 * N + n0 + bN4];

    float acc[8][8];
#pragma unroll
    for (int r = 0; r < 8; r++)
#pragma unroll
        for (int c = 0; c < 8; c++) acc[r][c] = 0.f;

    for (int k0 = 0; k0 < K; k0 += BK) {
        As[aKq0 + 0][aRow0] = aReg[0].x;
        As[aKq0 + 1][aRow0] = aReg[0].y;
        As[aKq0 + 2][aRow0] = aReg[0].z;
        As[aKq0 + 3][aRow0] = aReg[0].w;
        As[aKq0 + 0][aRow1] = aReg[1].x;
        As[aKq0 + 1][aRow1] = aReg[1].y;
        As[aKq0 + 2][aRow1] = aReg[1].z;
        As[aKq0 + 3][aRow1] = aReg[1].w;
        *(float4*)&Bs[bKr0][bN4] = bReg[0];
        *(float4*)&Bs[bKr1][bN4] = bReg[1];
        __syncthreads();

        if (k0 + BK < K) {
            int kn = k0 + BK;
            aReg[0] = *(const float4*)&A[(size_t)(m0 + aRow0) * K + kn + aKq0];
            aReg[1] = *(const float4*)&A[(size_t)(m0 + aRow1) * K + kn + aKq0];
            bReg[0] = *(const float4*)&B[(size_t)(kn + bKr0) * N + n0 + bN4];
            bReg[1] = *(const float4*)&B[(size_t)(kn + bKr1) * N + n0 + bN4];
        }

#pragma unroll
        for (int kk = 0; kk < BK; kk++) {
            float a[8], b[8];
            float4 a0 = *(const float4*)&As[kk][ty * 8];
            float4 a1 = *(const float4*)&As[kk][ty * 8 + 4];
            float4 b0 = *(const float4*)&Bs[kk][tx * 8];
            float4 b1 = *(const float4*)&Bs[kk][tx * 8 + 4];
            a[0]=a0.x; a[1]=a0.y; a[2]=a0.z; a[3]=a0.w;
            a[4]=a1.x; a[5]=a1.y; a[6]=a1.z; a[7]=a1.w;
            b[0]=b0.x; b[1]=b0.y; b[2]=b0.z; b[3]=b0.w;
            b[4]=b1.x; b[5]=b1.y; b[6]=b1.z; b[7]=b1.w;
#pragma unroll
            for (int r = 0; r < 8; r++)
#pragma unroll
                for (int c = 0; c < 8; c++)
                    acc[r][c] += a[r] * b[c];
        }
        __syncthreads();
    }

    float bb[8];
#pragma unroll
    for (int c = 0; c < 8; c++) bb[c] = bias[n0 + tx * 8 + c];
#pragma unroll
    for (int r = 0; r < 8; r++) {
        int m = m0 + ty * 8 + r;
#pragma unroll
        for (int c = 0; c < 8; c += 4) {
            float4 v;
            v.x = acc[r][c + 0] + bb[c + 0];
            v.y = acc[r][c + 1] + bb[c + 1];
            v.z = acc[r][c + 2] + bb[c + 2];
            v.w = acc[r][c + 3] + bb[c + 3];
            *(float4*)&Cmat[(size_t)m * N + n0 + tx * 8 + c] = v;
        }
    }
}

// ---------------------------------------------------------------------------
// Fixup attention (proven SIMT, round-2): runs ONLY if *flag != 0.
// ---------------------------------------------------------------------------
#define LDT 68

__global__ __launch_bounds__(256) void attn_fix_kernel(const int* __restrict__ flag)
{
    if (*(volatile const int*)flag == 0) return;

    extern __shared__ float sm[];
    float* Qt = sm;
    float* Kt = Qt + 64 * LDT;
    float* Vss = Kt + 64 * LDT;
    float* Pss = Vss + 64 * LDT;

    const int tid = threadIdx.x;
    const int tx = tid & 15;
    const int ty = tid >> 4;
    const int pair = blockIdx.y;
    const int h = pair >> 4;
    const int t = pair & 15;
    const int q0 = blockIdx.x * 64;

#pragma unroll
    for (int i = 0; i < 16; i++) {
        int idx = tid + 256 * i;
        int q = idx >> 6;
        int d = idx & 63;
        Qt[d * LDT + q] =
            g_qkv[(size_t)(t * HW_DIM + q0 + q) * QKV_N + h * HD + d] * 0.125f;
    }

    float mrow[4], lrow[4];
#pragma unroll
    for (int r = 0; r < 4; r++) { mrow[r] = -CUDART_INF_F; lrow[r] = 0.f; }

    float o[4][4];
#pragma unroll
    for (int r = 0; r < 4; r++)
#pragma unroll
        for (int c = 0; c < 4; c++) o[r][c] = 0.f;

    for (int k0 = 0; k0 < HW_DIM; k0 += 64) {
        __syncthreads();
#pragma unroll
        for (int i = 0; i < 16; i++) {
            int idx = tid + 256 * i;
            int kk = idx >> 6;
            int d  = idx & 63;
            size_t base = (size_t)(t * HW_DIM + k0 + kk) * QKV_N + h * HD + d;
            Kt[d * LDT + kk] = g_qkv[base + C_DIM];
            Vss[kk * LDT + d] = g_qkv[base + 2 * C_DIM];
        }
        __syncthreads();

        float s[4][4];
#pragma unroll
        for (int r = 0; r < 4; r++)
#pragma unroll
            for (int c = 0; c < 4; c++) s[r][c] = 0.f;
#pragma unroll
        for (int d = 0; d < 64; d++) {
            float4 a = *(const float4*)&Qt[d * LDT + 4 * ty];
            float4 b = *(const float4*)&Kt[d * LDT + 4 * tx];
            s[0][0] += a.x*b.x; s[0][1] += a.x*b.y; s[0][2] += a.x*b.z; s[0][3] += a.x*b.w;
            s[1][0] += a.y*b.x; s[1][1] += a.y*b.y; s[1][2] += a.y*b.z; s[1][3] += a.y*b.w;
            s[2][0] += a.z*b.x; s[2][1] += a.z*b.y; s[2][2] += a.z*b.z; s[2][3] += a.z*b.w;
            s[3][0] += a.w*b.x; s[3][1] += a.w*b.y; s[3][2] += a.w*b.z; s[3][3] += a.w*b.w;
        }

#pragma unroll
        for (int r = 0; r < 4; r++) {
            float lm = fmaxf(fmaxf(s[r][0], s[r][1]), fmaxf(s[r][2], s[r][3]));
#pragma unroll
            for (int off = 8; off; off >>= 1)
                lm = fmaxf(lm, __shfl_xor_sync(0xffffffffu, lm, off, 16));
            float mn = fmaxf(mrow[r], lm);
            float alpha = __expf(mrow[r] - mn);
            mrow[r] = mn;

            float rs = 0.f;
#pragma unroll
            for (int c = 0; c < 4; c++) {
                float p = __expf(s[r][c] - mn);
                s[r][c] = p;
                rs += p;
            }
#pragma unroll
            for (int off = 8; off; off >>= 1)
                rs += __shfl_xor_sync(0xffffffffu, rs, off, 16);
            lrow[r] = lrow[r] * alpha + rs;

            int qi = 4 * ty + r;
            float4 pv; pv.x = s[r][0]; pv.y = s[r][1]; pv.z = s[r][2]; pv.w = s[r][3];
            *(float4*)&Pss[qi * LDT + 4 * tx] = pv;
#pragma unroll
            for (int c = 0; c < 4; c++) o[r][c] *= alpha;
        }
        __syncwarp();

#pragma unroll
        for (int kk = 0; kk < 64; kk += 4) {
            float4 pr[4];
#pragma unroll
            for (int r = 0; r < 4; r++)
                pr[r] = *(const float4*)&Pss[(4 * ty + r) * LDT + kk];

            float4 v;
            v = *(const float4*)&Vss[(kk + 0) * LDT + 4 * tx];
            o[0][0]+=pr[0].x*v.x; o[0][1]+=pr[0].x*v.y; o[0][2]+=pr[0].x*v.z; o[0][3]+=pr[0].x*v.w;
            o[1][0]+=pr[1].x*v.x; o[1][1]+=pr[1].x*v.y; o[1][2]+=pr[1].x*v.z; o[1][3]+=pr[1].x*v.w;
            o[2][0]+=pr[2].x*v.x; o[2][1]+=pr[2].x*v.y; o[2][2]+=pr[2].x*v.z; o[2][3]+=pr[2].x*v.w;
            o[3][0]+=pr[3].x*v.x; o[3][1]+=pr[3].x*v.y; o[3][2]+=pr[3].x*v.z; o[3][3]+=pr[3].x*v.w;
            v = *(const float4*)&Vss[(kk + 1) * LDT + 4 * tx];
            o[0][0]+=pr[0].y*v.x; o[0][1]+=pr[0].y*v.y; o[0][2]+=pr[0].y*v.z; o[0][3]+=pr[0].y*v.w;
            o[1][0]+=pr[1].y*v.x; o[1][1]+=pr[1].y*v.y; o[1][2]+=pr[1].y*v.z; o[1][3]+=pr[1].y*v.w;
            o[2][0]+=pr[2].y*v.x; o[2][1]+=pr[2].y*v.y; o[2][2]+=pr[2].y*v.z; o[2][3]+=pr[2].y*v.w;
            o[3][0]+=pr[3].y*v.x; o[3][1]+=pr[3].y*v.y; o[3][2]+=pr[3].y*v.z; o[3][3]+=pr[3].y*v.w;
            v = *(const float4*)&Vss[(kk + 2) * LDT + 4 * tx];
            o[0][0]+=pr[0].z*v.x; o[0][1]+=pr[0].z*v.y; o[0][2]+=pr[0].z*v.z; o[0][3]+=pr[0].z*v.w;
            o[1][0]+=pr[1].z*v.x; o[1][1]+=pr[1].z*v.y; o[1][2]+=pr[1].z*v.z; o[1][3]+=pr[1].z*v.w;
            o[2][0]+=pr[2].z*v.x; o[2][1]+=pr[2].z*v.y; o[2][2]+=pr[2].z*v.z; o[2][3]+=pr[2].z*v.w;
            o[3][0]+=pr[3].z*v.x; o[3][1]+=pr[3].z*v.y; o[3][2]+=pr[3].z*v.z; o[3][3]+=pr[3].z*v.w;
            v = *(const float4*)&Vss[(kk + 3) * LDT + 4 * tx];
            o[0][0]+=pr[0].w*v.x; o[0][1]+=pr[0].w*v.y; o[0][2]+=pr[0].w*v.z; o[0][3]+=pr[0].w*v.w;
            o[1][0]+=pr[1].w*v.x; o[1][1]+=pr[1].w*v.y; o[1][2]+=pr[1].w*v.z; o[1][3]+=pr[1].w*v.w;
            o[2][0]+=pr[2].w*v.x; o[2][1]+=pr[2].w*v.y; o[2][2]+=pr[2].w*v.z; o[2][3]+=pr[2].w*v.w;
            o[3][0]+=pr[3].w*v.x; o[3][1]+=pr[3].w*v.y; o[3][2]+=pr[3].w*v.z; o[3][3]+=pr[3].w*v.w;
        }
    }

#pragma unroll
    for (int r = 0; r < 4; r++) {
        int qi = 4 * ty + r;
        float inv = 1.f / lrow[r];
        float4 v;
        v.x = o[r][0] * inv;
        v.y = o[r][1] * inv;
        v.z = o[r][2] * inv;
        v.w = o[r][3] * inv;
        size_t idx = ((size_t)(h * HW_DIM + q0 + qi) * T_DIM + t) * HD + 4 * tx;
        *(float4*)&g_attn[idx] = v;
    }
}

// ---------------------------------------------------------------------------

extern "C" void kernel_launch(void* const* d_in, const int* in_sizes, int n_in,
                              void* d_out, int out_size)
{
    (void)in_sizes; (void)n_in; (void)out_size;
    const float* x    = (const float*)d_in[0];
    const float* Wqkv = (const float*)d_in[1];
    const float* bqkv = (const float*)d_in[2];
    const float* Wout = (const float*)d_in[3];
    const float* bout = (const float*)d_in[4];
    float* out = (float*)d_out;

    float* qkv_ptr  = nullptr;
    float* attn_ptr = nullptr;
    int*   bad_ptr  = nullptr;
    cudaGetSymbolAddress((void**)&qkv_ptr,  g_qkv);
    cudaGetSymbolAddress((void**)&attn_ptr, g_attn);
    cudaGetSymbolAddress((void**)&bad_ptr,  g_bad);

    cudaFuncSetAttribute(mma_gemm_kernel,
                         cudaFuncAttributeMaxDynamicSharedMemorySize, GEMM_SMEM_BYTES);
    cudaFuncSetAttribute(mma_attn_kernel,
                         cudaFuncAttributeMaxDynamicSharedMemorySize, ATTN_SMEM_BYTES);
    const int fix_smem = (int)((size_t)(4 * 64 * LDT) * sizeof(float));
    cudaFuncSetAttribute(attn_fix_kernel,
                         cudaFuncAttributeMaxDynamicSharedMemorySize, fix_smem);

    // Zero probe flags (async memset is graph-capturable)
    cudaMemsetAsync(bad_ptr, 0, 4 * sizeof(int));

    // 1) QKV projection (mma.sync tf32) + probe + conditional SIMT repair
    {
        dim3 grid(QKV_N / 128, M_ROWS / 128);
        mma_gemm_kernel<<<grid, 256, GEMM_SMEM_BYTES>>>(x, Wqkv, bqkv, qkv_ptr,
                                                        M_ROWS, QKV_N, C_DIM);
        probe_kernel<<<64, 256>>>(x, Wqkv, bqkv, qkv_ptr,
                                  M_ROWS, QKV_N, C_DIM, bad_ptr);
        gemm_bias_fix_kernel<<<grid, 256>>>(x, Wqkv, bqkv, qkv_ptr,
                                            M_ROWS, QKV_N, C_DIM, bad_ptr);
    }

    // 2) Attention (mma.sync tf32 v4: cp.async pipelined) + probe + repair
    {
        dim3 grid(HW_DIM / 128, NH * T_DIM);
        mma_attn_kernel<<<grid, 256, ATTN_SMEM_BYTES>>>();
        attn_probe_kernel<<<64, 256>>>(bad_ptr + 2);
        dim3 fgrid(HW_DIM / 64, NH * T_DIM);
        attn_fix_kernel<<<fgrid, 256, fix_smem>>>(bad_ptr + 2);
    }

    // 3) Output projection (mma.sync tf32) + probe + conditional SIMT repair
    {
        dim3 grid(C_DIM / 128, M_ROWS / 128);
        mma_gemm_kernel<<<grid, 256, GEMM_SMEM_BYTES>>>(attn_ptr, Wout, bout, out,
                                                        M_ROWS, C_DIM, C_DIM);
        probe_kernel<<<64, 256>>>(attn_ptr, Wout, bout, out,
                                  M_ROWS, C_DIM, C_DIM, bad_ptr + 1);
        gemm_bias_fix_kernel<<<grid, 256>>>(attn_ptr, Wout, bout, out,
                                            M_ROWS, C_DIM, C_DIM, bad_ptr + 1);
    }
}